// round 13
// baseline (speedup 1.0000x reference)
#include <cuda_runtime.h>
#include <cuda_bf16.h>
#include <cuda_fp16.h>
#include <math.h>
#include <stdint.h>

#define NROI 1024
#define NCLS 21
#define APP  1024
#define DF   128
#define NH   16
#define DK   64

typedef unsigned long long ull;
typedef unsigned int u32;

// ---------------- f32x2 packed-math helpers (sm_103a) -------------------------
__device__ __forceinline__ ull pk2(float lo, float hi) {
    ull r; asm("mov.b64 %0,{%1,%2};" : "=l"(r) : "f"(lo), "f"(hi)); return r;
}
__device__ __forceinline__ float2 upk(ull v) {
    float2 f; asm("mov.b64 {%0,%1},%2;" : "=f"(f.x), "=f"(f.y) : "l"(v)); return f;
}
__device__ __forceinline__ void fma2(ull &c, ull a, ull b) {
    asm("fma.rn.f32x2 %0,%1,%2,%0;" : "+l"(c) : "l"(a), "l"(b));
}

// ---------------- HMMA m16n8k16 bf16 ------------------------------------------
__device__ __forceinline__ void mma_bf16(float* c, const u32* a, const u32* b) {
    asm volatile("mma.sync.aligned.m16n8k16.row.col.f32.bf16.bf16.f32 "
        "{%0,%1,%2,%3},{%4,%5,%6,%7},{%8,%9},{%0,%1,%2,%3};"
        : "+f"(c[0]), "+f"(c[1]), "+f"(c[2]), "+f"(c[3])
        : "r"(a[0]), "r"(a[1]), "r"(a[2]), "r"(a[3]), "r"(b[0]), "r"(b[1]));
}

// ---------------- scratch (device globals; no allocation allowed) -------------
__device__ __half g_Sh[NH * NROI * NROI];     // 32 MB scores fp16 [h][m][n]
__device__ __align__(16) __nv_bfloat16 g_Kh[NH*NROI*DK], g_Kl[NH*NROI*DK];
__device__ __align__(16) __nv_bfloat16 g_Qh[NH*NROI*DK], g_Ql[NH*NROI*DK];
__device__ __align__(16) float g_emb[NROI * DF];
__device__ __align__(16) float g_vl[NH * NROI];
__device__ __align__(16) float g_wvl[NH * DF];
__device__ float g_bvl[NH];
__device__ float g_prob[NROI], g_sprob[NROI], g_sflw[NROI];
__device__ float g_bbox[NROI * 4], g_sbbox[NROI * 4];
__device__ __align__(16) float4 g_geoA[NROI];   // cx, cy, log w, log h
__device__ __align__(8)  float2 g_geoB[NROI];   // 1/w, 1/h
__device__ int   g_label[NROI], g_slabel[NROI], g_order[NROI];

// ---------------- K1: per-ROI decode (blocks 0-3) + wvl (blocks 4-19) ---------
__global__ __launch_bounds__(256) void k_front(const float* __restrict__ roi,
                                               const float* __restrict__ cls_loc,
                                               const float* __restrict__ score,
                                               const int*   __restrict__ size,
                                               const float* __restrict__ wv_w,
                                               const float* __restrict__ wv_b,
                                               const float* __restrict__ lw) {
    __shared__ float lwh[DK];
    int b = blockIdx.x, t = threadIdx.x;
    if (b < 4) {
        int i = b * 256 + t;
        const float* s = score + i * NCLS;
        float mx = -1e30f; int am = 0;
        for (int c = 0; c < NCLS; c++) { float v = s[c]; if (v > mx) { mx = v; am = c; } }
        float sum = 0.f;
        for (int c = 0; c < NCLS; c++) sum += expf(s[c] - mx);
        g_prob[i] = 1.0f / sum;
        g_label[i] = am;
        float y0 = roi[i*4+0], x0 = roi[i*4+1], y1 = roi[i*4+2], x1 = roi[i*4+3];
        float h = y1 - y0, w = x1 - x0;
        float cy = y0 + 0.5f * h, cx = x0 + 0.5f * w;
        const float* l = cls_loc + i * (NCLS*4) + am * 4;
        float dy = l[0]*0.1f, dx = l[1]*0.1f, dh = l[2]*0.2f, dw = l[3]*0.2f;
        float ncy = dy*h + cy, ncx = dx*w + cx;
        float nh = expf(dh)*h, nw = expf(dw)*w;
        float b0 = ncy - 0.5f*nh, b1 = ncx - 0.5f*nw, b2 = ncy + 0.5f*nh, b3 = ncx + 0.5f*nw;
        // reference clamp quirk: even class -> all coords clamp to size[0], odd -> size[1]
        float lim = ((am & 1) == 0) ? (float)size[0] : (float)size[1];
        b0 = fminf(fmaxf(b0, 0.f), lim); b1 = fminf(fmaxf(b1, 0.f), lim);
        b2 = fminf(fmaxf(b2, 0.f), lim); b3 = fminf(fmaxf(b3, 0.f), lim);
        g_bbox[i*4+0]=b0; g_bbox[i*4+1]=b1; g_bbox[i*4+2]=b2; g_bbox[i*4+3]=b3;
        return;
    }
    int h = b - 4;
    if (t < DK) lwh[t] = lw[h * DK + t];
    __syncthreads();
    int d = t >> 1, half = t & 1;
    const float4* W  = (const float4*)(wv_w + (h * DF + d) * DK + half * 32);
    float a = 0.f;
    #pragma unroll
    for (int q = 0; q < 8; q++) {
        float4 w4 = W[q];
        const float* l4 = lwh + half * 32 + q * 4;
        a += w4.x*l4[0] + w4.y*l4[1] + w4.z*l4[2] + w4.w*l4[3];
    }
    a += __shfl_xor_sync(0xffffffffu, a, 1);
    if (!half) g_wvl[h * DF + d] = a;
    if (t < 32) {
        float pb = wv_b[h*DK + t] * lwh[t] + wv_b[h*DK + t + 32] * lwh[t + 32];
        #pragma unroll
        for (int o = 16; o; o >>= 1) pb += __shfl_xor_sync(0xffffffffu, pb, o);
        if (t == 0) g_bvl[h] = pb;
    }
}

// ---------------- K2: stable descending rank + scatter ------------------------
__global__ __launch_bounds__(256) void k_rank() {
    __shared__ float sp[NROI];
    int t = threadIdx.x;
    int i = blockIdx.x * 256 + t;
    for (int j = t; j < NROI; j += 256) sp[j] = g_prob[j];
    __syncthreads();
    float p = sp[i];
    int r = 0;
    for (int j = 0; j < NROI; j++) {
        float pj = sp[j];
        r += (pj > p) || (pj == p && j < i);
    }
    g_order[r]  = i;
    g_sprob[r]  = p;
    g_slabel[r] = g_label[i];
    float b0=g_bbox[i*4+0], b1=g_bbox[i*4+1], b2=g_bbox[i*4+2], b3=g_bbox[i*4+3];
    g_sbbox[r*4+0]=b0; g_sbbox[r*4+1]=b1; g_sbbox[r*4+2]=b2; g_sbbox[r*4+3]=b3;
    float cx = (b0+b2)*0.5f, cy = (b1+b3)*0.5f;
    float w  = (b2-b0)+1.0f, h  = (b3-b1)+1.0f;
    g_geoA[r] = make_float4(cx, cy, logf(w), logf(h));
    g_geoB[r] = make_float2(1.0f / w, 1.0f / h);
}

// ---------------- K3: emb = sf@feat_w + RE@rank_w + biases  (BM=8, 256 thr) ---
__global__ __launch_bounds__(256) void k_emb(const float* __restrict__ app,
                                             const float* __restrict__ rank_w,
                                             const float* __restrict__ rank_b,
                                             const float* __restrict__ feat_w,
                                             const float* __restrict__ feat_b,
                                             const float* __restrict__ lw) {
    __shared__ __align__(16) float arow[8][APP];
    __shared__ __align__(16) float rerow[8][APP];
    __shared__ int   s_oi[8];
    __shared__ float s_pl[8];
    __shared__ float s_part[8][DF];
    int i0 = blockIdx.x * 8, t = threadIdx.x;
    if (t < 8) s_oi[t] = g_order[i0 + t];
    __syncthreads();
    int row = t >> 5, lane = t & 31;
    {
        const float4* src = (const float4*)(app + s_oi[row] * APP);
        const float4* lw4 = (const float4*)lw;
        float pl = 0.f;
        #pragma unroll
        for (int q = 0; q < 8; q++) {
            int j4 = lane + q * 32;
            float4 a = src[j4];
            *(float4*)&arow[row][j4 * 4] = a;
            float4 l = lw4[j4];
            pl += a.x*l.x + a.y*l.y + a.z*l.z + a.w*l.w;
        }
        #pragma unroll
        for (int o = 16; o; o >>= 1) pl += __shfl_xor_sync(0xffffffffu, pl, o);
        if (lane == 0) s_pl[row] = pl;
    }
    const float LOGW = 6.90775527898f / 512.0f;
    #pragma unroll
    for (int fi = 0; fi < 2; fi++) {
        int f = t + fi * 256;
        float a = expf(-(float)f * LOGW);
        float s0, c0, sa, ca;
        sincosf((float)i0 * a, &s0, &c0);
        sincosf(a, &sa, &ca);
        #pragma unroll
        for (int r = 0; r < 8; r++) {
            rerow[r][f] = s0; rerow[r][f + 512] = c0;
            float s1 = s0*ca + c0*sa, c1 = c0*ca - s0*sa;
            s0 = s1; c0 = c1;
        }
    }
    __syncthreads();
    int col = t & 127, kh = t >> 7;
    ull acc[8];
    #pragma unroll
    for (int r = 0; r < 8; r++) acc[r] = 0ull;
    int jbase = kh * 512;
    for (int j4 = 0; j4 < 128; j4++) {
        int jb = jbase + j4 * 4;
        ull fp01 = pk2(feat_w[(jb+0)*DF + col], feat_w[(jb+1)*DF + col]);
        ull fp23 = pk2(feat_w[(jb+2)*DF + col], feat_w[(jb+3)*DF + col]);
        ull rp01 = pk2(rank_w[(jb+0)*DF + col], rank_w[(jb+1)*DF + col]);
        ull rp23 = pk2(rank_w[(jb+2)*DF + col], rank_w[(jb+3)*DF + col]);
        #pragma unroll
        for (int r = 0; r < 8; r++) {
            ulonglong2 a2 = *(const ulonglong2*)&arow[r][jb];
            ulonglong2 e2 = *(const ulonglong2*)&rerow[r][jb];
            fma2(acc[r], a2.x, fp01); fma2(acc[r], a2.y, fp23);
            fma2(acc[r], e2.x, rp01); fma2(acc[r], e2.y, rp23);
        }
    }
    if (kh == 0) {
        #pragma unroll
        for (int r = 0; r < 8; r++) {
            float2 v = upk(acc[r]);
            s_part[r][col] = v.x + v.y;
        }
    }
    __syncthreads();
    if (kh == 1) {
        float bias = feat_b[col] + rank_b[col];
        #pragma unroll
        for (int r = 0; r < 8; r++) {
            float2 v = upk(acc[r]);
            g_emb[(i0 + r) * DF + col] = v.x + v.y + s_part[r][col] + bias;
        }
    }
    if (t < 8) g_sflw[i0 + t] = s_pl[t];
}

// ---------------- K3b: vl[h][n] = emb[n].wvl[h] + bvl[h] (warp per n) ---------
__global__ __launch_bounds__(256) void k_vl() {
    int w = threadIdx.x >> 5, lane = threadIdx.x & 31;
    int n = blockIdx.x * 8 + w;
    float4 e4 = *(const float4*)(g_emb + n * DF + lane * 4);
    #pragma unroll
    for (int h = 0; h < NH; h++) {
        float4 wv = *(const float4*)(g_wvl + h * DF + lane * 4);
        float s = e4.x*wv.x + e4.y*wv.y + e4.z*wv.z + e4.w*wv.w;
        #pragma unroll
        for (int o = 16; o; o >>= 1) s += __shfl_xor_sync(0xffffffffu, s, o);
        if (lane == 0) g_vl[(h << 10) + n] = s + g_bvl[h];
    }
}

// ---------------- K4: k/q projections: BM=32, 1 col/thread --------------------
// grid (8 col-chunks, 32 row-chunks), 256 thr; weight L2 traffic 32 MB total
__global__ __launch_bounds__(256) void k_kqv(const float* __restrict__ wk_w,
                                             const float* __restrict__ wk_b,
                                             const float* __restrict__ wq_w,
                                             const float* __restrict__ wq_b) {
    __shared__ __align__(16) float es[DF][36];   // [d][row], stride 36 keeps 16B align
    int i0 = blockIdx.y * 32, t = threadIdx.x;
    int warp = t >> 5, lane = t & 31;
    #pragma unroll
    for (int rr = 0; rr < 4; rr++) {
        int row = warp * 4 + rr;
        float4 v = *(const float4*)(g_emb + (i0 + row) * DF + lane * 4);
        int d0 = lane * 4;
        es[d0 + 0][row] = v.x; es[d0 + 1][row] = v.y;
        es[d0 + 2][row] = v.z; es[d0 + 3][row] = v.w;
    }
    __syncthreads();
    int p = blockIdx.x * 256 + t;
    bool isK = (p < 1024);
    int pp = isK ? p : p - 1024;
    int h = pp >> 6, kk = pp & 63;
    const float* W = (isK ? wk_w : wq_w) + h * DF * DK + kk;
    float bias = (isK ? wk_b : wq_b)[pp];
    ull acc[16];
    #pragma unroll
    for (int q = 0; q < 16; q++) acc[q] = 0ull;
    #pragma unroll 4
    for (int d = 0; d < DF; d++) {
        float w = W[d << 6];
        ull wd = pk2(w, w);
        #pragma unroll
        for (int q = 0; q < 8; q++) {
            ulonglong2 a2 = *(const ulonglong2*)&es[d][q * 4];
            fma2(acc[2*q],     a2.x, wd);
            fma2(acc[2*q + 1], a2.y, wd);
        }
    }
    __nv_bfloat16* Hh = isK ? g_Kh : g_Qh;
    __nv_bfloat16* Hl = isK ? g_Kl : g_Ql;
    #pragma unroll
    for (int q = 0; q < 16; q++) {
        float2 v = upk(acc[q]);
        #pragma unroll
        for (int e = 0; e < 2; e++) {
            float val = ((e == 0) ? v.x : v.y) + bias;
            int idx = ((h << 10) + i0 + 2*q + e) * DK + kk;
            __nv_bfloat16 hi = __float2bfloat16(val);
            __nv_bfloat16 lo = __float2bfloat16(val - __bfloat162float(hi));
            Hh[idx] = hi; Hl[idx] = lo;
        }
    }
}

// ---------------- K5: HMMA bf16-split score GEMM -> fp16 S --------------------
#define LDP 33
__global__ __launch_bounds__(256) void k_score_mma() {
    extern __shared__ __align__(16) u32 sm[];
    u32* KHs = sm;
    u32* KLs = sm + 128 * LDP;
    u32* QHs = sm + 2 * 128 * LDP;
    u32* QLs = sm + 2 * 128 * LDP + 64 * LDP;
    int t = threadIdx.x;
    int nt = blockIdx.x, mt = blockIdx.y, h = blockIdx.z;
    const u32* gKH = (const u32*)g_Kh + ((h << 10) + mt * 128) * 32;
    const u32* gKL = (const u32*)g_Kl + ((h << 10) + mt * 128) * 32;
    const u32* gQH = (const u32*)g_Qh + ((h << 10) + nt * 64) * 32;
    const u32* gQL = (const u32*)g_Ql + ((h << 10) + nt * 64) * 32;
    #pragma unroll
    for (int it = 0; it < 16; it++) {
        int idx = t + it * 256;
        int row = idx >> 5, c = idx & 31;
        KHs[row * LDP + c] = gKH[idx];
        KLs[row * LDP + c] = gKL[idx];
    }
    #pragma unroll
    for (int it = 0; it < 8; it++) {
        int idx = t + it * 256;
        int row = idx >> 5, c = idx & 31;
        QHs[row * LDP + c] = gQH[idx];
        QLs[row * LDP + c] = gQL[idx];
    }
    __syncthreads();
    int wid = t >> 5, lane = t & 31;
    int m0 = (wid >> 1) * 32, n0 = (wid & 1) * 32;
    int r = lane >> 2, cp2 = (lane & 3) * 2;
    float acc[2][4][4];
    #pragma unroll
    for (int i = 0; i < 2; i++)
        #pragma unroll
        for (int j = 0; j < 4; j++)
            #pragma unroll
            for (int e = 0; e < 4; e++) acc[i][j][e] = 0.f;
    #pragma unroll
    for (int kc = 0; kc < 4; kc++) {
        int cb = kc * 8 + (cp2 >> 1);
        u32 ah[2][4], al[2][4];
        #pragma unroll
        for (int i = 0; i < 2; i++) {
            int ra = m0 + i * 16 + r;
            ah[i][0] = KHs[ra * LDP + cb];       al[i][0] = KLs[ra * LDP + cb];
            ah[i][1] = KHs[(ra+8) * LDP + cb];   al[i][1] = KLs[(ra+8) * LDP + cb];
            ah[i][2] = KHs[ra * LDP + cb + 4];   al[i][2] = KLs[ra * LDP + cb + 4];
            ah[i][3] = KHs[(ra+8) * LDP + cb+4]; al[i][3] = KLs[(ra+8) * LDP + cb+4];
        }
        u32 bh[4][2], bl[4][2];
        #pragma unroll
        for (int j = 0; j < 4; j++) {
            int rb = n0 + j * 8 + r;
            bh[j][0] = QHs[rb * LDP + cb];     bl[j][0] = QLs[rb * LDP + cb];
            bh[j][1] = QHs[rb * LDP + cb + 4]; bl[j][1] = QLs[rb * LDP + cb + 4];
        }
        #pragma unroll
        for (int i = 0; i < 2; i++)
            #pragma unroll
            for (int j = 0; j < 4; j++) {
                mma_bf16(acc[i][j], ah[i], bh[j]);
                mma_bf16(acc[i][j], ah[i], bl[j]);
                mma_bf16(acc[i][j], al[i], bh[j]);
            }
    }
    #pragma unroll
    for (int i = 0; i < 2; i++) {
        int m = mt * 128 + m0 + i * 16 + r;
        #pragma unroll
        for (int j = 0; j < 4; j++) {
            __half* dst = g_Sh + (h << 20) + (m << 10) + nt * 64 + n0 + j * 8 + cp2;
            *(__half2*)dst = __floats2half2_rn(acc[i][j][0] * 0.125f, acc[i][j][1] * 0.125f);
            *(__half2*)(dst + (8 << 10)) = __floats2half2_rn(acc[i][j][2] * 0.125f, acc[i][j][3] * 0.125f);
        }
    }
}

// ---------------- K6: fused geo prior + product softmax + vl + output ---------
__global__ __launch_bounds__(256) void k_attn(const float* __restrict__ wg_w,
                                              const float* __restrict__ wg_b,
                                              const float* __restrict__ logit_b,
                                              float* __restrict__ out) {
    extern __shared__ __align__(16) float sh[];
    float* G  = sh;                       // 16*1024
    ull* wgp  = (ull*)(sh + NH * NROI);   // 16*32 packed pairs
    __shared__ float wgb_s[NH];
    __shared__ float hred[NH];
    int m = blockIdx.x, t = threadIdx.x;
    for (int idx = t; idx < NH * 32; idx += 256) {
        int h = idx >> 5, j = idx & 31;
        float lo, hi;
        if (j < 16) { lo = wg_w[h*64 + 2*j];            hi = wg_w[h*64 + 2*j + 1]; }
        else { int jj = j - 16; lo = wg_w[h*64 + 32 + 2*jj]; hi = wg_w[h*64 + 32 + 2*jj + 1]; }
        wgp[idx] = pk2(lo, hi);
    }
    if (t < NH) wgb_s[t] = wg_b[t];
    float4 gm = g_geoA[m];
    float2 gi = g_geoB[m];
    __syncthreads();
    const float dmf[8] = {1.0f, 0.42169650342f, 0.17782794100f, 0.07498942093f,
                          0.03162277660f, 0.01333521432f, 0.00562341325f, 0.00237137371f};
    for (int n = t; n < NROI; n += 256) {
        float4 gn = g_geoA[n];
        float base4[4];
        base4[0] = 100.f * __logf(fmaxf(fabsf((gm.x - gn.x) * gi.x), 1e-3f));
        base4[1] = 100.f * __logf(fmaxf(fabsf((gm.y - gn.y) * gi.y), 1e-3f));
        base4[2] = 100.f * (gm.z - gn.z);
        base4[3] = 100.f * (gm.w - gn.w);
        ull ep[32];
        #pragma unroll
        for (int j2 = 0; j2 < 16; j2++) {
            int gi0 = 2 * j2, gi1 = gi0 + 1;
            float s0, c0, s1, c1;
            __sincosf(base4[gi0 >> 3] * dmf[gi0 & 7], &s0, &c0);
            __sincosf(base4[gi1 >> 3] * dmf[gi1 & 7], &s1, &c1);
            ep[j2]      = pk2(s0, s1);
            ep[16 + j2] = pk2(c0, c1);
        }
        for (int h = 0; h < NH; h++) {
            ull acc = pk2(wgb_s[h], 0.f);
            const ulonglong2* w2 = (const ulonglong2*)(wgp + h * 32);
            #pragma unroll
            for (int j2 = 0; j2 < 16; j2++) {
                ulonglong2 w = w2[j2];
                fma2(acc, ep[2 * j2],     w.x);
                fma2(acc, ep[2 * j2 + 1], w.y);
            }
            float2 f = upk(acc);
            G[(h << 10) + n] = fmaxf(f.x + f.y, 1e-6f);
        }
    }
    __syncthreads();
    int warp = t >> 5, lane = t & 31;
    for (int h = warp; h < NH; h += 8) {
        const uint4* S4 = (const uint4*)(g_Sh + (h << 20) + (m << 10));  // 8 halves each
        const float* vh = g_vl + (h << 10);
        const float* Gh = G + (h << 10);
        float ss = 0.f, ps = 0.f;
        #pragma unroll
        for (int it = 0; it < 4; it++) {
            int i8 = it * 32 + lane;
            int n0 = i8 * 8;
            uint4 sv = S4[i8];
            float4 va = *(const float4*)(vh + n0);
            float4 vb = *(const float4*)(vh + n0 + 4);
            float4 ga = *(const float4*)(Gh + n0);
            float4 gb = *(const float4*)(Gh + n0 + 4);
            float2 s0 = __half22float2(*(const __half2*)&sv.x);
            float2 s1 = __half22float2(*(const __half2*)&sv.y);
            float2 s2 = __half22float2(*(const __half2*)&sv.z);
            float2 s3 = __half22float2(*(const __half2*)&sv.w);
            float w0 = ga.x * __expf(fminf(s0.x, 60.f));
            float w1 = ga.y * __expf(fminf(s0.y, 60.f));
            float w2 = ga.z * __expf(fminf(s1.x, 60.f));
            float w3 = ga.w * __expf(fminf(s1.y, 60.f));
            float w4 = gb.x * __expf(fminf(s2.x, 60.f));
            float w5 = gb.y * __expf(fminf(s2.y, 60.f));
            float w6 = gb.z * __expf(fminf(s3.x, 60.f));
            float w7 = gb.w * __expf(fminf(s3.y, 60.f));
            ss += (w0 + w1 + w2 + w3) + (w4 + w5 + w6 + w7);
            ps += w0*va.x + w1*va.y + w2*va.z + w3*va.w
                + w4*vb.x + w5*vb.y + w6*vb.z + w7*vb.w;
        }
        #pragma unroll
        for (int o = 16; o; o >>= 1) {
            ss += __shfl_xor_sync(0xffffffffu, ss, o);
            ps += __shfl_xor_sync(0xffffffffu, ps, o);
        }
        if (lane == 0) hred[h] = ps / ss;
    }
    __syncthreads();
    if (t == 0) {
        float a = 0.f;
        for (int h = 0; h < NH; h++) a += hred[h];
        float x = a + g_sflw[m] + logit_b[0];
        float s1 = 1.0f / (1.0f + expf(-x));
        out[m] = s1 * g_sprob[m];
        out[NROI + m] = (float)(g_slabel[m] - 1);
        #pragma unroll
        for (int j = 0; j < 4; j++)
            out[2 * NROI + m * 4 + j] = g_sbbox[m * 4 + j];
    }
}

// ---------------- launch -------------------------------------------------------
extern "C" void kernel_launch(void* const* d_in, const int* in_sizes, int n_in,
                              void* d_out, int out_size) {
    const float* sample_roi  = (const float*)d_in[0];
    const float* roi_cls_loc = (const float*)d_in[1];
    const float* roi_score   = (const float*)d_in[2];
    const float* app         = (const float*)d_in[3];
    const int*   size        = (const int*)  d_in[4];
    const float* rank_w      = (const float*)d_in[5];
    const float* rank_b      = (const float*)d_in[6];
    const float* feat_w      = (const float*)d_in[7];
    const float* feat_b      = (const float*)d_in[8];
    const float* logit_w     = (const float*)d_in[9];
    const float* logit_b     = (const float*)d_in[10];
    const float* wg_w        = (const float*)d_in[11];
    const float* wg_b        = (const float*)d_in[12];
    const float* wk_w        = (const float*)d_in[13];
    const float* wk_b        = (const float*)d_in[14];
    const float* wq_w        = (const float*)d_in[15];
    const float* wq_b        = (const float*)d_in[16];
    const float* wv_w        = (const float*)d_in[17];
    const float* wv_b        = (const float*)d_in[18];
    float* out = (float*)d_out;

    const int score_smem = (2 * 128 * LDP + 2 * 64 * LDP) * (int)sizeof(u32); // 50688
    const int attn_smem  = (NH * NROI) * 4 + (NH * 32) * 8;                   // 69632
    cudaFuncSetAttribute(k_score_mma, cudaFuncAttributeMaxDynamicSharedMemorySize, score_smem);
    cudaFuncSetAttribute(k_attn, cudaFuncAttributeMaxDynamicSharedMemorySize, attn_smem);

    k_front<<<20, 256>>>(sample_roi, roi_cls_loc, roi_score, size, wv_w, wv_b, logit_w);
    k_rank<<<4, 256>>>();
    k_emb<<<NROI / 8, 256>>>(app, rank_w, rank_b, feat_w, feat_b, logit_w);
    k_vl<<<128, 256>>>();
    k_kqv<<<dim3(8, 32), 256>>>(wk_w, wk_b, wq_w, wq_b);
    k_score_mma<<<dim3(16, 8, 16), 256, score_smem>>>();
    k_attn<<<NROI, 256, attn_smem>>>(wg_w, wg_b, logit_b, out);
}

// round 14
// speedup vs baseline: 1.0213x; 1.0213x over previous
#include <cuda_runtime.h>
#include <cuda_bf16.h>
#include <cuda_fp16.h>
#include <math.h>
#include <stdint.h>

#define NROI 1024
#define NCLS 21
#define APP  1024
#define DF   128
#define NH   16
#define DK   64

typedef unsigned long long ull;
typedef unsigned int u32;

// ---------------- f32x2 packed-math helpers (sm_103a) -------------------------
__device__ __forceinline__ ull pk2(float lo, float hi) {
    ull r; asm("mov.b64 %0,{%1,%2};" : "=l"(r) : "f"(lo), "f"(hi)); return r;
}
__device__ __forceinline__ float2 upk(ull v) {
    float2 f; asm("mov.b64 {%0,%1},%2;" : "=f"(f.x), "=f"(f.y) : "l"(v)); return f;
}
__device__ __forceinline__ void fma2(ull &c, ull a, ull b) {
    asm("fma.rn.f32x2 %0,%1,%2,%0;" : "+l"(c) : "l"(a), "l"(b));
}

// ---------------- HMMA m16n8k16 bf16 ------------------------------------------
__device__ __forceinline__ void mma_bf16(float* c, const u32* a, const u32* b) {
    asm volatile("mma.sync.aligned.m16n8k16.row.col.f32.bf16.bf16.f32 "
        "{%0,%1,%2,%3},{%4,%5,%6,%7},{%8,%9},{%0,%1,%2,%3};"
        : "+f"(c[0]), "+f"(c[1]), "+f"(c[2]), "+f"(c[3])
        : "r"(a[0]), "r"(a[1]), "r"(a[2]), "r"(a[3]), "r"(b[0]), "r"(b[1]));
}

// ---------------- scratch (device globals; no allocation allowed) -------------
__device__ __half g_Sh[NH * NROI * NROI];     // 32 MB scores fp16 [h][m][n]
__device__ __align__(16) __nv_bfloat16 g_Kh[NH*NROI*DK], g_Kl[NH*NROI*DK];
__device__ __align__(16) __nv_bfloat16 g_Qh[NH*NROI*DK], g_Ql[NH*NROI*DK];
__device__ __align__(16) float g_emb[NROI * DF];
__device__ __align__(16) float g_vl[NH * NROI];
__device__ __align__(16) float g_wvl[NH * DF];
__device__ float g_bvl[NH];
__device__ float g_prob[NROI], g_sprob[NROI], g_sflw[NROI];
__device__ float g_bbox[NROI * 4], g_sbbox[NROI * 4];
__device__ __align__(16) float4 g_geoA[NROI];   // cx, cy, log w, log h
__device__ __align__(8)  float2 g_geoB[NROI];   // 1/w, 1/h
__device__ int   g_label[NROI], g_slabel[NROI], g_order[NROI];

// ---------------- K1: per-ROI softmax/argmax/bbox decode ----------------------
__global__ __launch_bounds__(256) void k_front(const float* __restrict__ roi,
                                               const float* __restrict__ cls_loc,
                                               const float* __restrict__ score,
                                               const int*   __restrict__ size) {
    int i = blockIdx.x * 256 + threadIdx.x;
    const float* s = score + i * NCLS;
    float mx = -1e30f; int am = 0;
    for (int c = 0; c < NCLS; c++) { float v = s[c]; if (v > mx) { mx = v; am = c; } }
    float sum = 0.f;
    for (int c = 0; c < NCLS; c++) sum += expf(s[c] - mx);
    g_prob[i] = 1.0f / sum;
    g_label[i] = am;
    float y0 = roi[i*4+0], x0 = roi[i*4+1], y1 = roi[i*4+2], x1 = roi[i*4+3];
    float h = y1 - y0, w = x1 - x0;
    float cy = y0 + 0.5f * h, cx = x0 + 0.5f * w;
    const float* l = cls_loc + i * (NCLS*4) + am * 4;
    float dy = l[0]*0.1f, dx = l[1]*0.1f, dh = l[2]*0.2f, dw = l[3]*0.2f;
    float ncy = dy*h + cy, ncx = dx*w + cx;
    float nh = expf(dh)*h, nw = expf(dw)*w;
    float b0 = ncy - 0.5f*nh, b1 = ncx - 0.5f*nw, b2 = ncy + 0.5f*nh, b3 = ncx + 0.5f*nw;
    // reference clamp quirk: even class -> all coords clamp to size[0], odd -> size[1]
    float lim = ((am & 1) == 0) ? (float)size[0] : (float)size[1];
    b0 = fminf(fmaxf(b0, 0.f), lim); b1 = fminf(fmaxf(b1, 0.f), lim);
    b2 = fminf(fmaxf(b2, 0.f), lim); b3 = fminf(fmaxf(b3, 0.f), lim);
    g_bbox[i*4+0]=b0; g_bbox[i*4+1]=b1; g_bbox[i*4+2]=b2; g_bbox[i*4+3]=b3;
}

// ---------------- K1b: wvl[h] = wv_w[h] @ lw_h --------------------------------
__global__ __launch_bounds__(256) void k_wvlk(const float* __restrict__ wv_w,
                                              const float* __restrict__ wv_b,
                                              const float* __restrict__ lw) {
    __shared__ float lwh[DK];
    int h = blockIdx.x, t = threadIdx.x;
    if (t < DK) lwh[t] = lw[h * DK + t];
    __syncthreads();
    int d = t >> 1, half = t & 1;
    const float4* W  = (const float4*)(wv_w + (h * DF + d) * DK + half * 32);
    float a = 0.f;
    #pragma unroll
    for (int q = 0; q < 8; q++) {
        float4 w4 = W[q];
        const float* l4 = lwh + half * 32 + q * 4;
        a += w4.x*l4[0] + w4.y*l4[1] + w4.z*l4[2] + w4.w*l4[3];
    }
    a += __shfl_xor_sync(0xffffffffu, a, 1);
    if (!half) g_wvl[h * DF + d] = a;
    if (t < 32) {
        float pb = wv_b[h*DK + t] * lwh[t] + wv_b[h*DK + t + 32] * lwh[t + 32];
        #pragma unroll
        for (int o = 16; o; o >>= 1) pb += __shfl_xor_sync(0xffffffffu, pb, o);
        if (t == 0) g_bvl[h] = pb;
    }
}

// ---------------- K2: stable descending rank + scatter ------------------------
__global__ __launch_bounds__(256) void k_rank() {
    __shared__ float sp[NROI];
    int t = threadIdx.x;
    int i = blockIdx.x * 256 + t;
    for (int j = t; j < NROI; j += 256) sp[j] = g_prob[j];
    __syncthreads();
    float p = sp[i];
    int r = 0;
    for (int j = 0; j < NROI; j++) {
        float pj = sp[j];
        r += (pj > p) || (pj == p && j < i);
    }
    g_order[r]  = i;
    g_sprob[r]  = p;
    g_slabel[r] = g_label[i];
    float b0=g_bbox[i*4+0], b1=g_bbox[i*4+1], b2=g_bbox[i*4+2], b3=g_bbox[i*4+3];
    g_sbbox[r*4+0]=b0; g_sbbox[r*4+1]=b1; g_sbbox[r*4+2]=b2; g_sbbox[r*4+3]=b3;
    float cx = (b0+b2)*0.5f, cy = (b1+b3)*0.5f;
    float w  = (b2-b0)+1.0f, h  = (b3-b1)+1.0f;
    g_geoA[r] = make_float4(cx, cy, logf(w), logf(h));
    g_geoB[r] = make_float2(1.0f / w, 1.0f / h);
}

// ---------------- K3: emb GEMM  (grid 128 rowblocks x 2 colhalves) ------------
// per block: 8 rows, 64 cols, 4-way k-split across thread groups
__global__ __launch_bounds__(256) void k_emb(const float* __restrict__ app,
                                             const float* __restrict__ rank_w,
                                             const float* __restrict__ rank_b,
                                             const float* __restrict__ feat_w,
                                             const float* __restrict__ feat_b,
                                             const float* __restrict__ lw) {
    __shared__ __align__(16) float arow[8][APP];
    __shared__ __align__(16) float rerow[8][APP];
    __shared__ int   s_oi[8];
    __shared__ float s_pl[8];
    __shared__ float s_part[3][8][64];
    int i0 = blockIdx.x * 8, ch = blockIdx.y, t = threadIdx.x;
    if (t < 8) s_oi[t] = g_order[i0 + t];
    __syncthreads();
    int row = t >> 5, lane = t & 31;
    {
        const float4* src = (const float4*)(app + s_oi[row] * APP);
        const float4* lw4 = (const float4*)lw;
        float pl = 0.f;
        #pragma unroll
        for (int q = 0; q < 8; q++) {
            int j4 = lane + q * 32;
            float4 a = src[j4];
            *(float4*)&arow[row][j4 * 4] = a;
            float4 l = lw4[j4];
            pl += a.x*l.x + a.y*l.y + a.z*l.z + a.w*l.w;
        }
        #pragma unroll
        for (int o = 16; o; o >>= 1) pl += __shfl_xor_sync(0xffffffffu, pl, o);
        if (lane == 0) s_pl[row] = pl;
    }
    const float LOGW = 6.90775527898f / 512.0f;
    #pragma unroll
    for (int fi = 0; fi < 2; fi++) {
        int f = t + fi * 256;
        float a = expf(-(float)f * LOGW);
        float s0, c0, sa, ca;
        sincosf((float)i0 * a, &s0, &c0);
        sincosf(a, &sa, &ca);
        #pragma unroll
        for (int r = 0; r < 8; r++) {
            rerow[r][f] = s0; rerow[r][f + 512] = c0;
            float s1 = s0*ca + c0*sa, c1 = c0*ca - s0*sa;
            s0 = s1; c0 = c1;
        }
    }
    __syncthreads();
    int cl = t & 63, col = ch * 64 + cl, kh = t >> 6;   // kh in 0..3
    ull acc[8];
    #pragma unroll
    for (int r = 0; r < 8; r++) acc[r] = 0ull;
    int jbase = kh * 256;
    for (int j4 = 0; j4 < 64; j4++) {
        int jb = jbase + j4 * 4;
        ull fp01 = pk2(feat_w[(jb+0)*DF + col], feat_w[(jb+1)*DF + col]);
        ull fp23 = pk2(feat_w[(jb+2)*DF + col], feat_w[(jb+3)*DF + col]);
        ull rp01 = pk2(rank_w[(jb+0)*DF + col], rank_w[(jb+1)*DF + col]);
        ull rp23 = pk2(rank_w[(jb+2)*DF + col], rank_w[(jb+3)*DF + col]);
        #pragma unroll
        for (int r = 0; r < 8; r++) {
            ulonglong2 a2 = *(const ulonglong2*)&arow[r][jb];
            ulonglong2 e2 = *(const ulonglong2*)&rerow[r][jb];
            fma2(acc[r], a2.x, fp01); fma2(acc[r], a2.y, fp23);
            fma2(acc[r], e2.x, rp01); fma2(acc[r], e2.y, rp23);
        }
    }
    if (kh < 3) {
        #pragma unroll
        for (int r = 0; r < 8; r++) {
            float2 v = upk(acc[r]);
            s_part[kh][r][cl] = v.x + v.y;
        }
    }
    __syncthreads();
    if (kh == 3) {
        float bias = feat_b[col] + rank_b[col];
        #pragma unroll
        for (int r = 0; r < 8; r++) {
            float2 v = upk(acc[r]);
            g_emb[(i0 + r) * DF + col] = v.x + v.y + s_part[0][r][cl]
                                       + s_part[1][r][cl] + s_part[2][r][cl] + bias;
        }
    }
    if (ch == 0 && t < 8) g_sflw[i0 + t] = s_pl[t];
}

// ---------------- K3b: vl — thread per (h, n); smem operands ------------------
__global__ __launch_bounds__(256) void k_vl() {
    __shared__ __align__(16) float ebt[16][132];
    __shared__ __align__(16) float wvs[16][132];
    int n0 = blockIdx.x * 16, t = threadIdx.x;
    for (int i = t; i < 512; i += 256) {
        int r = i >> 5, c4 = i & 31;
        *(float4*)&ebt[r][c4 * 4] = *(const float4*)(g_emb + (n0 + r) * DF + c4 * 4);
        *(float4*)&wvs[r][c4 * 4] = *(const float4*)(g_wvl + r * DF + c4 * 4);
    }
    __syncthreads();
    int h = t >> 4, nr = t & 15;
    float acc = g_bvl[h];
    #pragma unroll 8
    for (int d4 = 0; d4 < 32; d4++) {
        float4 e = *(const float4*)&ebt[nr][d4 * 4];
        float4 w = *(const float4*)&wvs[h][d4 * 4];
        acc += e.x*w.x + e.y*w.y + e.z*w.z + e.w*w.w;
    }
    g_vl[(h << 10) + n0 + nr] = acc;
}

// ---------------- K4: k/q projections: BM=32, 1 col/thread --------------------
__global__ __launch_bounds__(256) void k_kqv(const float* __restrict__ wk_w,
                                             const float* __restrict__ wk_b,
                                             const float* __restrict__ wq_w,
                                             const float* __restrict__ wq_b) {
    __shared__ __align__(16) float es[DF][36];
    int i0 = blockIdx.y * 32, t = threadIdx.x;
    int warp = t >> 5, lane = t & 31;
    #pragma unroll
    for (int rr = 0; rr < 4; rr++) {
        int row = warp * 4 + rr;
        float4 v = *(const float4*)(g_emb + (i0 + row) * DF + lane * 4);
        int d0 = lane * 4;
        es[d0 + 0][row] = v.x; es[d0 + 1][row] = v.y;
        es[d0 + 2][row] = v.z; es[d0 + 3][row] = v.w;
    }
    __syncthreads();
    int p = blockIdx.x * 256 + t;
    bool isK = (p < 1024);
    int pp = isK ? p : p - 1024;
    int h = pp >> 6, kk = pp & 63;
    const float* W = (isK ? wk_w : wq_w) + h * DF * DK + kk;
    float bias = (isK ? wk_b : wq_b)[pp];
    ull acc[16];
    #pragma unroll
    for (int q = 0; q < 16; q++) acc[q] = 0ull;
    #pragma unroll 4
    for (int d = 0; d < DF; d++) {
        float w = W[d << 6];
        ull wd = pk2(w, w);
        #pragma unroll
        for (int q = 0; q < 8; q++) {
            ulonglong2 a2 = *(const ulonglong2*)&es[d][q * 4];
            fma2(acc[2*q],     a2.x, wd);
            fma2(acc[2*q + 1], a2.y, wd);
        }
    }
    __nv_bfloat16* Hh = isK ? g_Kh : g_Qh;
    __nv_bfloat16* Hl = isK ? g_Kl : g_Ql;
    #pragma unroll
    for (int q = 0; q < 16; q++) {
        float2 v = upk(acc[q]);
        #pragma unroll
        for (int e = 0; e < 2; e++) {
            float val = ((e == 0) ? v.x : v.y) + bias;
            int idx = ((h << 10) + i0 + 2*q + e) * DK + kk;
            __nv_bfloat16 hi = __float2bfloat16(val);
            __nv_bfloat16 lo = __float2bfloat16(val - __bfloat162float(hi));
            Hh[idx] = hi; Hl[idx] = lo;
        }
    }
}

// ---------------- K5: HMMA bf16-split score GEMM -> fp16 S --------------------
#define LDP 33
__global__ __launch_bounds__(256) void k_score_mma() {
    extern __shared__ __align__(16) u32 sm[];
    u32* KHs = sm;
    u32* KLs = sm + 128 * LDP;
    u32* QHs = sm + 2 * 128 * LDP;
    u32* QLs = sm + 2 * 128 * LDP + 64 * LDP;
    int t = threadIdx.x;
    int nt = blockIdx.x, mt = blockIdx.y, h = blockIdx.z;
    const u32* gKH = (const u32*)g_Kh + ((h << 10) + mt * 128) * 32;
    const u32* gKL = (const u32*)g_Kl + ((h << 10) + mt * 128) * 32;
    const u32* gQH = (const u32*)g_Qh + ((h << 10) + nt * 64) * 32;
    const u32* gQL = (const u32*)g_Ql + ((h << 10) + nt * 64) * 32;
    #pragma unroll
    for (int it = 0; it < 16; it++) {
        int idx = t + it * 256;
        int row = idx >> 5, c = idx & 31;
        KHs[row * LDP + c] = gKH[idx];
        KLs[row * LDP + c] = gKL[idx];
    }
    #pragma unroll
    for (int it = 0; it < 8; it++) {
        int idx = t + it * 256;
        int row = idx >> 5, c = idx & 31;
        QHs[row * LDP + c] = gQH[idx];
        QLs[row * LDP + c] = gQL[idx];
    }
    __syncthreads();
    int wid = t >> 5, lane = t & 31;
    int m0 = (wid >> 1) * 32, n0 = (wid & 1) * 32;
    int r = lane >> 2, cp2 = (lane & 3) * 2;
    float acc[2][4][4];
    #pragma unroll
    for (int i = 0; i < 2; i++)
        #pragma unroll
        for (int j = 0; j < 4; j++)
            #pragma unroll
            for (int e = 0; e < 4; e++) acc[i][j][e] = 0.f;
    #pragma unroll
    for (int kc = 0; kc < 4; kc++) {
        int cb = kc * 8 + (cp2 >> 1);
        u32 ah[2][4], al[2][4];
        #pragma unroll
        for (int i = 0; i < 2; i++) {
            int ra = m0 + i * 16 + r;
            ah[i][0] = KHs[ra * LDP + cb];       al[i][0] = KLs[ra * LDP + cb];
            ah[i][1] = KHs[(ra+8) * LDP + cb];   al[i][1] = KLs[(ra+8) * LDP + cb];
            ah[i][2] = KHs[ra * LDP + cb + 4];   al[i][2] = KLs[ra * LDP + cb + 4];
            ah[i][3] = KHs[(ra+8) * LDP + cb+4]; al[i][3] = KLs[(ra+8) * LDP + cb+4];
        }
        u32 bh[4][2], bl[4][2];
        #pragma unroll
        for (int j = 0; j < 4; j++) {
            int rb = n0 + j * 8 + r;
            bh[j][0] = QHs[rb * LDP + cb];     bl[j][0] = QLs[rb * LDP + cb];
            bh[j][1] = QHs[rb * LDP + cb + 4]; bl[j][1] = QLs[rb * LDP + cb + 4];
        }
        #pragma unroll
        for (int i = 0; i < 2; i++)
            #pragma unroll
            for (int j = 0; j < 4; j++) {
                mma_bf16(acc[i][j], ah[i], bh[j]);
                mma_bf16(acc[i][j], ah[i], bl[j]);
                mma_bf16(acc[i][j], al[i], bh[j]);
            }
    }
    #pragma unroll
    for (int i = 0; i < 2; i++) {
        int m = mt * 128 + m0 + i * 16 + r;
        #pragma unroll
        for (int j = 0; j < 4; j++) {
            __half* dst = g_Sh + (h << 20) + (m << 10) + nt * 64 + n0 + j * 8 + cp2;
            *(__half2*)dst = __floats2half2_rn(acc[i][j][0] * 0.125f, acc[i][j][1] * 0.125f);
            *(__half2*)(dst + (8 << 10)) = __floats2half2_rn(acc[i][j][2] * 0.125f, acc[i][j][3] * 0.125f);
        }
    }
}

// ---------------- K6: fused geo prior + product softmax + vl + output ---------
__global__ __launch_bounds__(256) void k_attn(const float* __restrict__ wg_w,
                                              const float* __restrict__ wg_b,
                                              const float* __restrict__ logit_b,
                                              float* __restrict__ out) {
    extern __shared__ __align__(16) float sh[];
    float* G  = sh;                       // 16*1024
    ull* wgp  = (ull*)(sh + NH * NROI);   // 16*32 packed pairs
    __shared__ float wgb_s[NH];
    __shared__ float hred[NH];
    int m = blockIdx.x, t = threadIdx.x;
    for (int idx = t; idx < NH * 32; idx += 256) {
        int h = idx >> 5, j = idx & 31;
        float lo, hi;
        if (j < 16) { lo = wg_w[h*64 + 2*j];            hi = wg_w[h*64 + 2*j + 1]; }
        else { int jj = j - 16; lo = wg_w[h*64 + 32 + 2*jj]; hi = wg_w[h*64 + 32 + 2*jj + 1]; }
        wgp[idx] = pk2(lo, hi);
    }
    if (t < NH) wgb_s[t] = wg_b[t];
    float4 gm = g_geoA[m];
    float2 gi = g_geoB[m];
    __syncthreads();
    const float dmf[8] = {1.0f, 0.42169650342f, 0.17782794100f, 0.07498942093f,
                          0.03162277660f, 0.01333521432f, 0.00562341325f, 0.00237137371f};
    for (int n = t; n < NROI; n += 256) {
        float4 gn = g_geoA[n];
        float base4[4];
        base4[0] = 100.f * __logf(fmaxf(fabsf((gm.x - gn.x) * gi.x), 1e-3f));
        base4[1] = 100.f * __logf(fmaxf(fabsf((gm.y - gn.y) * gi.y), 1e-3f));
        base4[2] = 100.f * (gm.z - gn.z);
        base4[3] = 100.f * (gm.w - gn.w);
        ull ep[32];
        #pragma unroll
        for (int j2 = 0; j2 < 16; j2++) {
            int gi0 = 2 * j2, gi1 = gi0 + 1;
            float s0, c0, s1, c1;
            __sincosf(base4[gi0 >> 3] * dmf[gi0 & 7], &s0, &c0);
            __sincosf(base4[gi1 >> 3] * dmf[gi1 & 7], &s1, &c1);
            ep[j2]      = pk2(s0, s1);
            ep[16 + j2] = pk2(c0, c1);
        }
        for (int h = 0; h < NH; h++) {
            ull acc = pk2(wgb_s[h], 0.f);
            const ulonglong2* w2 = (const ulonglong2*)(wgp + h * 32);
            #pragma unroll
            for (int j2 = 0; j2 < 16; j2++) {
                ulonglong2 w = w2[j2];
                fma2(acc, ep[2 * j2],     w.x);
                fma2(acc, ep[2 * j2 + 1], w.y);
            }
            float2 f = upk(acc);
            G[(h << 10) + n] = fmaxf(f.x + f.y, 1e-6f);
        }
    }
    __syncthreads();
    int warp = t >> 5, lane = t & 31;
    for (int h = warp; h < NH; h += 8) {
        const uint4* S4 = (const uint4*)(g_Sh + (h << 20) + (m << 10));
        const float* vh = g_vl + (h << 10);
        const float* Gh = G + (h << 10);
        float ss = 0.f, ps = 0.f;
        #pragma unroll
        for (int it = 0; it < 4; it++) {
            int i8 = it * 32 + lane;
            int n0 = i8 * 8;
            uint4 sv = S4[i8];
            float4 va = *(const float4*)(vh + n0);
            float4 vb = *(const float4*)(vh + n0 + 4);
            float4 ga = *(const float4*)(Gh + n0);
            float4 gb = *(const float4*)(Gh + n0 + 4);
            float2 s0 = __half22float2(*(const __half2*)&sv.x);
            float2 s1 = __half22float2(*(const __half2*)&sv.y);
            float2 s2 = __half22float2(*(const __half2*)&sv.z);
            float2 s3 = __half22float2(*(const __half2*)&sv.w);
            float w0 = ga.x * __expf(fminf(s0.x, 60.f));
            float w1 = ga.y * __expf(fminf(s0.y, 60.f));
            float w2 = ga.z * __expf(fminf(s1.x, 60.f));
            float w3 = ga.w * __expf(fminf(s1.y, 60.f));
            float w4 = gb.x * __expf(fminf(s2.x, 60.f));
            float w5 = gb.y * __expf(fminf(s2.y, 60.f));
            float w6 = gb.z * __expf(fminf(s3.x, 60.f));
            float w7 = gb.w * __expf(fminf(s3.y, 60.f));
            ss += (w0 + w1 + w2 + w3) + (w4 + w5 + w6 + w7);
            ps += w0*va.x + w1*va.y + w2*va.z + w3*va.w
                + w4*vb.x + w5*vb.y + w6*vb.z + w7*vb.w;
        }
        #pragma unroll
        for (int o = 16; o; o >>= 1) {
            ss += __shfl_xor_sync(0xffffffffu, ss, o);
            ps += __shfl_xor_sync(0xffffffffu, ps, o);
        }
        if (lane == 0) hred[h] = ps / ss;
    }
    __syncthreads();
    if (t == 0) {
        float a = 0.f;
        for (int h = 0; h < NH; h++) a += hred[h];
        float x = a + g_sflw[m] + logit_b[0];
        float s1 = 1.0f / (1.0f + expf(-x));
        out[m] = s1 * g_sprob[m];
        out[NROI + m] = (float)(g_slabel[m] - 1);
        #pragma unroll
        for (int j = 0; j < 4; j++)
            out[2 * NROI + m * 4 + j] = g_sbbox[m * 4 + j];
    }
}

// ---------------- launch -------------------------------------------------------
extern "C" void kernel_launch(void* const* d_in, const int* in_sizes, int n_in,
                              void* d_out, int out_size) {
    const float* sample_roi  = (const float*)d_in[0];
    const float* roi_cls_loc = (const float*)d_in[1];
    const float* roi_score   = (const float*)d_in[2];
    const float* app         = (const float*)d_in[3];
    const int*   size        = (const int*)  d_in[4];
    const float* rank_w      = (const float*)d_in[5];
    const float* rank_b      = (const float*)d_in[6];
    const float* feat_w      = (const float*)d_in[7];
    const float* feat_b      = (const float*)d_in[8];
    const float* logit_w     = (const float*)d_in[9];
    const float* logit_b     = (const float*)d_in[10];
    const float* wg_w        = (const float*)d_in[11];
    const float* wg_b        = (const float*)d_in[12];
    const float* wk_w        = (const float*)d_in[13];
    const float* wk_b        = (const float*)d_in[14];
    const float* wq_w        = (const float*)d_in[15];
    const float* wq_b        = (const float*)d_in[16];
    const float* wv_w        = (const float*)d_in[17];
    const float* wv_b        = (const float*)d_in[18];
    float* out = (float*)d_out;

    const int score_smem = (2 * 128 * LDP + 2 * 64 * LDP) * (int)sizeof(u32); // 50688
    const int attn_smem  = (NH * NROI) * 4 + (NH * 32) * 8;                   // 69632
    cudaFuncSetAttribute(k_score_mma, cudaFuncAttributeMaxDynamicSharedMemorySize, score_smem);
    cudaFuncSetAttribute(k_attn, cudaFuncAttributeMaxDynamicSharedMemorySize, attn_smem);

    k_front<<<4, 256>>>(sample_roi, roi_cls_loc, roi_score, size);
    k_wvlk<<<NH, 256>>>(wv_w, wv_b, logit_w);
    k_rank<<<4, 256>>>();
    k_emb<<<dim3(128, 2), 256>>>(app, rank_w, rank_b, feat_w, feat_b, logit_w);  // profile slot 4
    k_kqv<<<dim3(8, 32), 256>>>(wk_w, wk_b, wq_w, wq_b);
    k_vl<<<64, 256>>>();
    k_score_mma<<<dim3(16, 8, 16), 256, score_smem>>>();
    k_attn<<<NROI, 256, attn_smem>>>(wg_w, wg_b, logit_b, out);
}

// round 15
// speedup vs baseline: 1.0321x; 1.0105x over previous
#include <cuda_runtime.h>
#include <cuda_bf16.h>
#include <cuda_fp16.h>
#include <math.h>
#include <stdint.h>

#define NROI 1024
#define NCLS 21
#define APP  1024
#define DF   128
#define NH   16
#define DK   64

typedef unsigned long long ull;
typedef unsigned int u32;

// ---------------- f32x2 packed-math helpers (sm_103a) -------------------------
__device__ __forceinline__ ull pk2(float lo, float hi) {
    ull r; asm("mov.b64 %0,{%1,%2};" : "=l"(r) : "f"(lo), "f"(hi)); return r;
}
__device__ __forceinline__ float2 upk(ull v) {
    float2 f; asm("mov.b64 {%0,%1},%2;" : "=f"(f.x), "=f"(f.y) : "l"(v)); return f;
}
__device__ __forceinline__ void fma2(ull &c, ull a, ull b) {
    asm("fma.rn.f32x2 %0,%1,%2,%0;" : "+l"(c) : "l"(a), "l"(b));
}

// ---------------- HMMA m16n8k16 bf16 ------------------------------------------
__device__ __forceinline__ void mma_bf16(float* c, const u32* a, const u32* b) {
    asm volatile("mma.sync.aligned.m16n8k16.row.col.f32.bf16.bf16.f32 "
        "{%0,%1,%2,%3},{%4,%5,%6,%7},{%8,%9},{%0,%1,%2,%3};"
        : "+f"(c[0]), "+f"(c[1]), "+f"(c[2]), "+f"(c[3])
        : "r"(a[0]), "r"(a[1]), "r"(a[2]), "r"(a[3]), "r"(b[0]), "r"(b[1]));
}

// ---------------- scratch (device globals; no allocation allowed) -------------
__device__ __half g_Sh[NH * NROI * NROI];     // 32 MB scores fp16 [h][m][n]
__device__ __align__(16) __nv_bfloat16 g_Kh[NH*NROI*DK], g_Kl[NH*NROI*DK];
__device__ __align__(16) __nv_bfloat16 g_Qh[NH*NROI*DK], g_Ql[NH*NROI*DK];
__device__ __align__(16) float g_emb[NROI * DF];
__device__ __align__(16) float g_vl[NH * NROI];
__device__ __align__(16) float g_wvl[NH * DF];
__device__ float g_bvl[NH];
__device__ float g_prob[NROI], g_sprob[NROI], g_sflw[NROI];
__device__ float g_bbox[NROI * 4], g_sbbox[NROI * 4];
__device__ __align__(16) float4 g_geoA[NROI];   // cx, cy, log w, log h
__device__ __align__(8)  float2 g_geoB[NROI];   // 1/w, 1/h
__device__ int   g_label[NROI], g_slabel[NROI], g_order[NROI];

// ---------------- K1: per-ROI softmax/argmax/bbox decode ----------------------
__global__ __launch_bounds__(256) void k_front(const float* __restrict__ roi,
                                               const float* __restrict__ cls_loc,
                                               const float* __restrict__ score,
                                               const int*   __restrict__ size) {
    int i = blockIdx.x * 256 + threadIdx.x;
    const float* s = score + i * NCLS;
    float mx = -1e30f; int am = 0;
    for (int c = 0; c < NCLS; c++) { float v = s[c]; if (v > mx) { mx = v; am = c; } }
    float sum = 0.f;
    for (int c = 0; c < NCLS; c++) sum += expf(s[c] - mx);
    g_prob[i] = 1.0f / sum;
    g_label[i] = am;
    float y0 = roi[i*4+0], x0 = roi[i*4+1], y1 = roi[i*4+2], x1 = roi[i*4+3];
    float h = y1 - y0, w = x1 - x0;
    float cy = y0 + 0.5f * h, cx = x0 + 0.5f * w;
    const float* l = cls_loc + i * (NCLS*4) + am * 4;
    float dy = l[0]*0.1f, dx = l[1]*0.1f, dh = l[2]*0.2f, dw = l[3]*0.2f;
    float ncy = dy*h + cy, ncx = dx*w + cx;
    float nh = expf(dh)*h, nw = expf(dw)*w;
    float b0 = ncy - 0.5f*nh, b1 = ncx - 0.5f*nw, b2 = ncy + 0.5f*nh, b3 = ncx + 0.5f*nw;
    // reference clamp quirk: even class -> all coords clamp to size[0], odd -> size[1]
    float lim = ((am & 1) == 0) ? (float)size[0] : (float)size[1];
    b0 = fminf(fmaxf(b0, 0.f), lim); b1 = fminf(fmaxf(b1, 0.f), lim);
    b2 = fminf(fmaxf(b2, 0.f), lim); b3 = fminf(fmaxf(b3, 0.f), lim);
    g_bbox[i*4+0]=b0; g_bbox[i*4+1]=b1; g_bbox[i*4+2]=b2; g_bbox[i*4+3]=b3;
}

// ---------------- K1b: wvl[h] = wv_w[h] @ lw_h --------------------------------
__global__ __launch_bounds__(256) void k_wvlk(const float* __restrict__ wv_w,
                                              const float* __restrict__ wv_b,
                                              const float* __restrict__ lw) {
    __shared__ float lwh[DK];
    int h = blockIdx.x, t = threadIdx.x;
    if (t < DK) lwh[t] = lw[h * DK + t];
    __syncthreads();
    int d = t >> 1, half = t & 1;
    const float4* W  = (const float4*)(wv_w + (h * DF + d) * DK + half * 32);
    float a = 0.f;
    #pragma unroll
    for (int q = 0; q < 8; q++) {
        float4 w4 = W[q];
        const float* l4 = lwh + half * 32 + q * 4;
        a += w4.x*l4[0] + w4.y*l4[1] + w4.z*l4[2] + w4.w*l4[3];
    }
    a += __shfl_xor_sync(0xffffffffu, a, 1);
    if (!half) g_wvl[h * DF + d] = a;
    if (t < 32) {
        float pb = wv_b[h*DK + t] * lwh[t] + wv_b[h*DK + t + 32] * lwh[t + 32];
        #pragma unroll
        for (int o = 16; o; o >>= 1) pb += __shfl_xor_sync(0xffffffffu, pb, o);
        if (t == 0) g_bvl[h] = pb;
    }
}

// ---------------- K2: stable descending rank + scatter ------------------------
__global__ __launch_bounds__(256) void k_rank() {
    __shared__ float sp[NROI];
    int t = threadIdx.x;
    int i = blockIdx.x * 256 + t;
    for (int j = t; j < NROI; j += 256) sp[j] = g_prob[j];
    __syncthreads();
    float p = sp[i];
    int r = 0;
    for (int j = 0; j < NROI; j++) {
        float pj = sp[j];
        r += (pj > p) || (pj == p && j < i);
    }
    g_order[r]  = i;
    g_sprob[r]  = p;
    g_slabel[r] = g_label[i];
    float b0=g_bbox[i*4+0], b1=g_bbox[i*4+1], b2=g_bbox[i*4+2], b3=g_bbox[i*4+3];
    g_sbbox[r*4+0]=b0; g_sbbox[r*4+1]=b1; g_sbbox[r*4+2]=b2; g_sbbox[r*4+3]=b3;
    float cx = (b0+b2)*0.5f, cy = (b1+b3)*0.5f;
    float w  = (b2-b0)+1.0f, h  = (b3-b1)+1.0f;
    g_geoA[r] = make_float4(cx, cy, logf(w), logf(h));
    g_geoB[r] = make_float2(1.0f / w, 1.0f / h);
}

// ---------------- K3: emb GEMM — 8 rows, 128 cols/block, 2 cols/thread --------
// 256 thr = 64 col-threads (cols c, c+64) x 4 k-segments (256 k each)
__global__ __launch_bounds__(256) void k_emb(const float* __restrict__ app,
                                             const float* __restrict__ rank_w,
                                             const float* __restrict__ rank_b,
                                             const float* __restrict__ feat_w,
                                             const float* __restrict__ feat_b,
                                             const float* __restrict__ lw) {
    __shared__ __align__(16) float arow[8][APP];
    __shared__ __align__(16) float rerow[8][APP];
    __shared__ int   s_oi[8];
    __shared__ float s_pl[8];
    __shared__ float s_part[3][8][DF];
    int i0 = blockIdx.x * 8, t = threadIdx.x;
    if (t < 8) s_oi[t] = g_order[i0 + t];
    __syncthreads();
    int row = t >> 5, lane = t & 31;
    {
        const float4* src = (const float4*)(app + s_oi[row] * APP);
        const float4* lw4 = (const float4*)lw;
        float pl = 0.f;
        #pragma unroll
        for (int q = 0; q < 8; q++) {
            int j4 = lane + q * 32;
            float4 a = src[j4];
            *(float4*)&arow[row][j4 * 4] = a;
            float4 l = lw4[j4];
            pl += a.x*l.x + a.y*l.y + a.z*l.z + a.w*l.w;
        }
        #pragma unroll
        for (int o = 16; o; o >>= 1) pl += __shfl_xor_sync(0xffffffffu, pl, o);
        if (lane == 0) s_pl[row] = pl;
    }
    const float LOGW = 6.90775527898f / 512.0f;
    #pragma unroll
    for (int fi = 0; fi < 2; fi++) {
        int f = t + fi * 256;
        float a = expf(-(float)f * LOGW);
        float s0, c0, sa, ca;
        sincosf((float)i0 * a, &s0, &c0);
        sincosf(a, &sa, &ca);
        #pragma unroll
        for (int r = 0; r < 8; r++) {
            rerow[r][f] = s0; rerow[r][f + 512] = c0;
            float s1 = s0*ca + c0*sa, c1 = c0*ca - s0*sa;
            s0 = s1; c0 = c1;
        }
    }
    __syncthreads();
    int c0 = t & 63, c1 = c0 + 64, kseg = t >> 6;   // kseg 0..3
    ull acc[8][2];
    #pragma unroll
    for (int r = 0; r < 8; r++) { acc[r][0] = 0ull; acc[r][1] = 0ull; }
    int jbase = kseg * 256;
    for (int j4 = 0; j4 < 64; j4++) {
        int jb = jbase + j4 * 4;
        const float* fw = feat_w + jb * DF;
        const float* rw = rank_w + jb * DF;
        ull fA01 = pk2(fw[c0],        fw[DF + c0]);
        ull fA23 = pk2(fw[2*DF + c0], fw[3*DF + c0]);
        ull rA01 = pk2(rw[c0],        rw[DF + c0]);
        ull rA23 = pk2(rw[2*DF + c0], rw[3*DF + c0]);
        ull fB01 = pk2(fw[c1],        fw[DF + c1]);
        ull fB23 = pk2(fw[2*DF + c1], fw[3*DF + c1]);
        ull rB01 = pk2(rw[c1],        rw[DF + c1]);
        ull rB23 = pk2(rw[2*DF + c1], rw[3*DF + c1]);
        #pragma unroll
        for (int r = 0; r < 8; r++) {
            ulonglong2 a2 = *(const ulonglong2*)&arow[r][jb];
            ulonglong2 e2 = *(const ulonglong2*)&rerow[r][jb];
            fma2(acc[r][0], a2.x, fA01); fma2(acc[r][0], a2.y, fA23);
            fma2(acc[r][0], e2.x, rA01); fma2(acc[r][0], e2.y, rA23);
            fma2(acc[r][1], a2.x, fB01); fma2(acc[r][1], a2.y, fB23);
            fma2(acc[r][1], e2.x, rB01); fma2(acc[r][1], e2.y, rB23);
        }
    }
    if (kseg < 3) {
        #pragma unroll
        for (int r = 0; r < 8; r++) {
            float2 v0 = upk(acc[r][0]);
            float2 v1 = upk(acc[r][1]);
            s_part[kseg][r][c0] = v0.x + v0.y;
            s_part[kseg][r][c1] = v1.x + v1.y;
        }
    }
    __syncthreads();
    if (kseg == 3) {
        float b0 = feat_b[c0] + rank_b[c0];
        float b1 = feat_b[c1] + rank_b[c1];
        #pragma unroll
        for (int r = 0; r < 8; r++) {
            float2 v0 = upk(acc[r][0]);
            float2 v1 = upk(acc[r][1]);
            g_emb[(i0 + r) * DF + c0] = v0.x + v0.y + s_part[0][r][c0]
                                      + s_part[1][r][c0] + s_part[2][r][c0] + b0;
            g_emb[(i0 + r) * DF + c1] = v1.x + v1.y + s_part[0][r][c1]
                                      + s_part[1][r][c1] + s_part[2][r][c1] + b1;
        }
    }
    if (t < 8) g_sflw[i0 + t] = s_pl[t];
}

// ---------------- K3b: vl — thread per (h, n); smem operands ------------------
__global__ __launch_bounds__(256) void k_vl() {
    __shared__ __align__(16) float ebt[16][132];
    __shared__ __align__(16) float wvs[16][132];
    int n0 = blockIdx.x * 16, t = threadIdx.x;
    for (int i = t; i < 512; i += 256) {
        int r = i >> 5, c4 = i & 31;
        *(float4*)&ebt[r][c4 * 4] = *(const float4*)(g_emb + (n0 + r) * DF + c4 * 4);
        *(float4*)&wvs[r][c4 * 4] = *(const float4*)(g_wvl + r * DF + c4 * 4);
    }
    __syncthreads();
    int h = t >> 4, nr = t & 15;
    float acc = g_bvl[h];
    #pragma unroll 8
    for (int d4 = 0; d4 < 32; d4++) {
        float4 e = *(const float4*)&ebt[nr][d4 * 4];
        float4 w = *(const float4*)&wvs[h][d4 * 4];
        acc += e.x*w.x + e.y*w.y + e.z*w.z + e.w*w.w;
    }
    g_vl[(h << 10) + n0 + nr] = acc;
}

// ---------------- K4: k/q projections: BM=32, 2 cols/thread -------------------
// grid (4 col-chunks of 512, 32 row-chunks); per d: 8 LDS.128 + 2 LDG + 32 fma2
__global__ __launch_bounds__(256) void k_kqv(const float* __restrict__ wk_w,
                                             const float* __restrict__ wk_b,
                                             const float* __restrict__ wq_w,
                                             const float* __restrict__ wq_b) {
    __shared__ __align__(16) float es[DF][36];
    int i0 = blockIdx.y * 32, t = threadIdx.x;
    int warp = t >> 5, lane = t & 31;
    #pragma unroll
    for (int rr = 0; rr < 4; rr++) {
        int row = warp * 4 + rr;
        float4 v = *(const float4*)(g_emb + (i0 + row) * DF + lane * 4);
        int d0 = lane * 4;
        es[d0 + 0][row] = v.x; es[d0 + 1][row] = v.y;
        es[d0 + 2][row] = v.z; es[d0 + 3][row] = v.w;
    }
    __syncthreads();
    int p0 = blockIdx.x * 512 + t;
    int p1 = p0 + 256;
    bool isK0 = (p0 < 1024), isK1 = (p1 < 1024);
    int pp0 = isK0 ? p0 : p0 - 1024, pp1 = isK1 ? p1 : p1 - 1024;
    int h0 = pp0 >> 6, kk0 = pp0 & 63;
    int h1 = pp1 >> 6, kk1 = pp1 & 63;
    const float* W0 = (isK0 ? wk_w : wq_w) + h0 * DF * DK + kk0;
    const float* W1 = (isK1 ? wk_w : wq_w) + h1 * DF * DK + kk1;
    float bias0 = (isK0 ? wk_b : wq_b)[pp0];
    float bias1 = (isK1 ? wk_b : wq_b)[pp1];
    ull acc[2][16];
    #pragma unroll
    for (int c = 0; c < 2; c++)
        #pragma unroll
        for (int q = 0; q < 16; q++) acc[c][q] = 0ull;
    #pragma unroll 2
    for (int d = 0; d < DF; d++) {
        float w0 = W0[d << 6], w1 = W1[d << 6];
        ull wd0 = pk2(w0, w0), wd1 = pk2(w1, w1);
        #pragma unroll
        for (int q = 0; q < 8; q++) {
            ulonglong2 a2 = *(const ulonglong2*)&es[d][q * 4];
            fma2(acc[0][2*q],     a2.x, wd0);
            fma2(acc[0][2*q + 1], a2.y, wd0);
            fma2(acc[1][2*q],     a2.x, wd1);
            fma2(acc[1][2*q + 1], a2.y, wd1);
        }
    }
    #pragma unroll
    for (int c = 0; c < 2; c++) {
        bool isK = (c == 0) ? isK0 : isK1;
        int h = (c == 0) ? h0 : h1, kk = (c == 0) ? kk0 : kk1;
        float bias = (c == 0) ? bias0 : bias1;
        __nv_bfloat16* Hh = isK ? g_Kh : g_Qh;
        __nv_bfloat16* Hl = isK ? g_Kl : g_Ql;
        #pragma unroll
        for (int q = 0; q < 16; q++) {
            float2 v = upk(acc[c][q]);
            #pragma unroll
            for (int e = 0; e < 2; e++) {
                float val = ((e == 0) ? v.x : v.y) + bias;
                int idx = ((h << 10) + i0 + 2*q + e) * DK + kk;
                __nv_bfloat16 hi = __float2bfloat16(val);
                __nv_bfloat16 lo = __float2bfloat16(val - __bfloat162float(hi));
                Hh[idx] = hi; Hl[idx] = lo;
            }
        }
    }
}

// ---------------- K5: HMMA bf16-split score GEMM -> fp16 S --------------------
#define LDP 33
__global__ __launch_bounds__(256) void k_score_mma() {
    extern __shared__ __align__(16) u32 sm[];
    u32* KHs = sm;
    u32* KLs = sm + 128 * LDP;
    u32* QHs = sm + 2 * 128 * LDP;
    u32* QLs = sm + 2 * 128 * LDP + 64 * LDP;
    int t = threadIdx.x;
    int nt = blockIdx.x, mt = blockIdx.y, h = blockIdx.z;
    const u32* gKH = (const u32*)g_Kh + ((h << 10) + mt * 128) * 32;
    const u32* gKL = (const u32*)g_Kl + ((h << 10) + mt * 128) * 32;
    const u32* gQH = (const u32*)g_Qh + ((h << 10) + nt * 64) * 32;
    const u32* gQL = (const u32*)g_Ql + ((h << 10) + nt * 64) * 32;
    #pragma unroll
    for (int it = 0; it < 16; it++) {
        int idx = t + it * 256;
        int row = idx >> 5, c = idx & 31;
        KHs[row * LDP + c] = gKH[idx];
        KLs[row * LDP + c] = gKL[idx];
    }
    #pragma unroll
    for (int it = 0; it < 8; it++) {
        int idx = t + it * 256;
        int row = idx >> 5, c = idx & 31;
        QHs[row * LDP + c] = gQH[idx];
        QLs[row * LDP + c] = gQL[idx];
    }
    __syncthreads();
    int wid = t >> 5, lane = t & 31;
    int m0 = (wid >> 1) * 32, n0 = (wid & 1) * 32;
    int r = lane >> 2, cp2 = (lane & 3) * 2;
    float acc[2][4][4];
    #pragma unroll
    for (int i = 0; i < 2; i++)
        #pragma unroll
        for (int j = 0; j < 4; j++)
            #pragma unroll
            for (int e = 0; e < 4; e++) acc[i][j][e] = 0.f;
    #pragma unroll
    for (int kc = 0; kc < 4; kc++) {
        int cb = kc * 8 + (cp2 >> 1);
        u32 ah[2][4], al[2][4];
        #pragma unroll
        for (int i = 0; i < 2; i++) {
            int ra = m0 + i * 16 + r;
            ah[i][0] = KHs[ra * LDP + cb];       al[i][0] = KLs[ra * LDP + cb];
            ah[i][1] = KHs[(ra+8) * LDP + cb];   al[i][1] = KLs[(ra+8) * LDP + cb];
            ah[i][2] = KHs[ra * LDP + cb + 4];   al[i][2] = KLs[ra * LDP + cb + 4];
            ah[i][3] = KHs[(ra+8) * LDP + cb+4]; al[i][3] = KLs[(ra+8) * LDP + cb+4];
        }
        u32 bh[4][2], bl[4][2];
        #pragma unroll
        for (int j = 0; j < 4; j++) {
            int rb = n0 + j * 8 + r;
            bh[j][0] = QHs[rb * LDP + cb];     bl[j][0] = QLs[rb * LDP + cb];
            bh[j][1] = QHs[rb * LDP + cb + 4]; bl[j][1] = QLs[rb * LDP + cb + 4];
        }
        #pragma unroll
        for (int i = 0; i < 2; i++)
            #pragma unroll
            for (int j = 0; j < 4; j++) {
                mma_bf16(acc[i][j], ah[i], bh[j]);
                mma_bf16(acc[i][j], ah[i], bl[j]);
                mma_bf16(acc[i][j], al[i], bh[j]);
            }
    }
    #pragma unroll
    for (int i = 0; i < 2; i++) {
        int m = mt * 128 + m0 + i * 16 + r;
        #pragma unroll
        for (int j = 0; j < 4; j++) {
            __half* dst = g_Sh + (h << 20) + (m << 10) + nt * 64 + n0 + j * 8 + cp2;
            *(__half2*)dst = __floats2half2_rn(acc[i][j][0] * 0.125f, acc[i][j][1] * 0.125f);
            *(__half2*)(dst + (8 << 10)) = __floats2half2_rn(acc[i][j][2] * 0.125f, acc[i][j][3] * 0.125f);
        }
    }
}

// ---------------- K6: fused geo prior + product softmax + vl + output ---------
__global__ __launch_bounds__(256) void k_attn(const float* __restrict__ wg_w,
                                              const float* __restrict__ wg_b,
                                              const float* __restrict__ logit_b,
                                              float* __restrict__ out) {
    extern __shared__ __align__(16) float sh[];
    float* G  = sh;                       // 16*1024
    ull* wgp  = (ull*)(sh + NH * NROI);   // 16*32 packed pairs
    __shared__ float wgb_s[NH];
    __shared__ float hred[NH];
    int m = blockIdx.x, t = threadIdx.x;
    for (int idx = t; idx < NH * 32; idx += 256) {
        int h = idx >> 5, j = idx & 31;
        float lo, hi;
        if (j < 16) { lo = wg_w[h*64 + 2*j];            hi = wg_w[h*64 + 2*j + 1]; }
        else { int jj = j - 16; lo = wg_w[h*64 + 32 + 2*jj]; hi = wg_w[h*64 + 32 + 2*jj + 1]; }
        wgp[idx] = pk2(lo, hi);
    }
    if (t < NH) wgb_s[t] = wg_b[t];
    float4 gm = g_geoA[m];
    float2 gi = g_geoB[m];
    __syncthreads();
    const float dmf[8] = {1.0f, 0.42169650342f, 0.17782794100f, 0.07498942093f,
                          0.03162277660f, 0.01333521432f, 0.00562341325f, 0.00237137371f};
    for (int n = t; n < NROI; n += 256) {
        float4 gn = g_geoA[n];
        float base4[4];
        base4[0] = 100.f * __logf(fmaxf(fabsf((gm.x - gn.x) * gi.x), 1e-3f));
        base4[1] = 100.f * __logf(fmaxf(fabsf((gm.y - gn.y) * gi.y), 1e-3f));
        base4[2] = 100.f * (gm.z - gn.z);
        base4[3] = 100.f * (gm.w - gn.w);
        ull ep[32];
        #pragma unroll
        for (int j2 = 0; j2 < 16; j2++) {
            int gi0 = 2 * j2, gi1 = gi0 + 1;
            float s0, c0, s1, c1;
            __sincosf(base4[gi0 >> 3] * dmf[gi0 & 7], &s0, &c0);
            __sincosf(base4[gi1 >> 3] * dmf[gi1 & 7], &s1, &c1);
            ep[j2]      = pk2(s0, s1);
            ep[16 + j2] = pk2(c0, c1);
        }
        for (int h = 0; h < NH; h++) {
            ull acc = pk2(wgb_s[h], 0.f);
            const ulonglong2* w2 = (const ulonglong2*)(wgp + h * 32);
            #pragma unroll
            for (int j2 = 0; j2 < 16; j2++) {
                ulonglong2 w = w2[j2];
                fma2(acc, ep[2 * j2],     w.x);
                fma2(acc, ep[2 * j2 + 1], w.y);
            }
            float2 f = upk(acc);
            G[(h << 10) + n] = fmaxf(f.x + f.y, 1e-6f);
        }
    }
    __syncthreads();
    int warp = t >> 5, lane = t & 31;
    for (int h = warp; h < NH; h += 8) {
        const uint4* S4 = (const uint4*)(g_Sh + (h << 20) + (m << 10));
        const float* vh = g_vl + (h << 10);
        const float* Gh = G + (h << 10);
        float ss = 0.f, ps = 0.f;
        #pragma unroll
        for (int it = 0; it < 4; it++) {
            int i8 = it * 32 + lane;
            int n0 = i8 * 8;
            uint4 sv = S4[i8];
            float4 va = *(const float4*)(vh + n0);
            float4 vb = *(const float4*)(vh + n0 + 4);
            float4 ga = *(const float4*)(Gh + n0);
            float4 gb = *(const float4*)(Gh + n0 + 4);
            float2 s0 = __half22float2(*(const __half2*)&sv.x);
            float2 s1 = __half22float2(*(const __half2*)&sv.y);
            float2 s2 = __half22float2(*(const __half2*)&sv.z);
            float2 s3 = __half22float2(*(const __half2*)&sv.w);
            float w0 = ga.x * __expf(fminf(s0.x, 60.f));
            float w1 = ga.y * __expf(fminf(s0.y, 60.f));
            float w2 = ga.z * __expf(fminf(s1.x, 60.f));
            float w3 = ga.w * __expf(fminf(s1.y, 60.f));
            float w4 = gb.x * __expf(fminf(s2.x, 60.f));
            float w5 = gb.y * __expf(fminf(s2.y, 60.f));
            float w6 = gb.z * __expf(fminf(s3.x, 60.f));
            float w7 = gb.w * __expf(fminf(s3.y, 60.f));
            ss += (w0 + w1 + w2 + w3) + (w4 + w5 + w6 + w7);
            ps += w0*va.x + w1*va.y + w2*va.z + w3*va.w
                + w4*vb.x + w5*vb.y + w6*vb.z + w7*vb.w;
        }
        #pragma unroll
        for (int o = 16; o; o >>= 1) {
            ss += __shfl_xor_sync(0xffffffffu, ss, o);
            ps += __shfl_xor_sync(0xffffffffu, ps, o);
        }
        if (lane == 0) hred[h] = ps / ss;
    }
    __syncthreads();
    if (t == 0) {
        float a = 0.f;
        for (int h = 0; h < NH; h++) a += hred[h];
        float x = a + g_sflw[m] + logit_b[0];
        float s1 = 1.0f / (1.0f + expf(-x));
        out[m] = s1 * g_sprob[m];
        out[NROI + m] = (float)(g_slabel[m] - 1);
        #pragma unroll
        for (int j = 0; j < 4; j++)
            out[2 * NROI + m * 4 + j] = g_sbbox[m * 4 + j];
    }
}

// ---------------- launch -------------------------------------------------------
extern "C" void kernel_launch(void* const* d_in, const int* in_sizes, int n_in,
                              void* d_out, int out_size) {
    const float* sample_roi  = (const float*)d_in[0];
    const float* roi_cls_loc = (const float*)d_in[1];
    const float* roi_score   = (const float*)d_in[2];
    const float* app         = (const float*)d_in[3];
    const int*   size        = (const int*)  d_in[4];
    const float* rank_w      = (const float*)d_in[5];
    const float* rank_b      = (const float*)d_in[6];
    const float* feat_w      = (const float*)d_in[7];
    const float* feat_b      = (const float*)d_in[8];
    const float* logit_w     = (const float*)d_in[9];
    const float* logit_b     = (const float*)d_in[10];
    const float* wg_w        = (const float*)d_in[11];
    const float* wg_b        = (const float*)d_in[12];
    const float* wk_w        = (const float*)d_in[13];
    const float* wk_b        = (const float*)d_in[14];
    const float* wq_w        = (const float*)d_in[15];
    const float* wq_b        = (const float*)d_in[16];
    const float* wv_w        = (const float*)d_in[17];
    const float* wv_b        = (const float*)d_in[18];
    float* out = (float*)d_out;

    const int score_smem = (2 * 128 * LDP + 2 * 64 * LDP) * (int)sizeof(u32); // 50688
    const int attn_smem  = (NH * NROI) * 4 + (NH * 32) * 8;                   // 69632
    cudaFuncSetAttribute(k_score_mma, cudaFuncAttributeMaxDynamicSharedMemorySize, score_smem);
    cudaFuncSetAttribute(k_attn, cudaFuncAttributeMaxDynamicSharedMemorySize, attn_smem);

    k_front<<<4, 256>>>(sample_roi, roi_cls_loc, roi_score, size);
    k_wvlk<<<NH, 256>>>(wv_w, wv_b, logit_w);
    k_rank<<<4, 256>>>();
    k_emb<<<128, 256>>>(app, rank_w, rank_b, feat_w, feat_b, logit_w);  // profile slot 4
    k_kqv<<<dim3(4, 32), 256>>>(wk_w, wk_b, wq_w, wq_b);
    k_vl<<<64, 256>>>();
    k_score_mma<<<dim3(16, 8, 16), 256, score_smem>>>();
    k_attn<<<NROI, 256, attn_smem>>>(wg_w, wg_b, logit_b, out);
}